// round 10
// baseline (speedup 1.0000x reference)
#include <cuda_runtime.h>

#define NB   4
#define NP   4096
#define TILE 128
#define RT   8
#define CT   8
#define CCH  4                                   // col chunk (register-liveness cap)
#define NMIN (2 * NB * NP)                       // 32768 mins: [gt | coord]
#define NBLK (NB * (NP / TILE) * (NP / TILE))    // 4096 blocks

// Scratch, zero-initialized at module load. Keys are ~float_bits(d) so the
// atomicMax identity is 0 — no init kernel needed. The last block resets
// everything to 0 so every graph replay starts clean.
__device__ unsigned g_key[NMIN];
__device__ unsigned g_count = 0;

__global__ __launch_bounds__(256, 1) void chamfer_fused_kernel(
    const float* __restrict__ coord, const float* __restrict__ gt,
    float* __restrict__ out)
{
    __shared__ float sgx[TILE], sgy[TILE], sgz[TILE], sgn[TILE];
    __shared__ float scx2[TILE], scy2[TILE], scz2[TILE], scn[TILE];
    __shared__ unsigned srowkey[TILE];
    __shared__ unsigned scolkey[TILE];
    __shared__ float red[8];
    __shared__ int is_last;

    const int b    = blockIdx.z;
    const int row0 = blockIdx.y * TILE;   // gt rows
    const int col0 = blockIdx.x * TILE;   // coord cols
    const int t    = threadIdx.x;

    // Stage tiles. Coord side pre-transformed: (-2x,-2y,-2z, |c|^2).
    if (t < TILE) {
        const float* p = gt + (size_t)(b * NP + row0 + t) * 3;
        const float x = p[0], y = p[1], z = p[2];
        sgx[t] = x; sgy[t] = y; sgz[t] = z;
        sgn[t] = fmaf(x, x, fmaf(y, y, z * z));
        scolkey[t] = 0u;
    } else {
        const int u = t - TILE;
        const float* p = coord + (size_t)(b * NP + col0 + u) * 3;
        const float x = p[0], y = p[1], z = p[2];
        scx2[u] = -2.0f * x; scy2[u] = -2.0f * y; scz2[u] = -2.0f * z;
        scn[u]  = fmaf(x, x, fmaf(y, y, z * z));
    }
    __syncthreads();

    const int ty = t >> 4;
    const int tx = t & 15;

    float rx[RT], ry[RT], rz[RT], rn[RT];
#pragma unroll
    for (int i = 0; i < RT; i++) {
        const int r = ty * RT + i;
        rx[i] = sgx[r]; ry[i] = sgy[r]; rz[i] = sgz[r]; rn[i] = sgn[r];
    }

    const float INF = __int_as_float(0x7F800000);
    float rmin[RT], cmin[CT];
#pragma unroll
    for (int i = 0; i < RT; i++) rmin[i] = INF;
#pragma unroll
    for (int j = 0; j < CT; j++) cmin[j] = INF;

    // d = (rn + cn) + rx*(-2cx) + ry*(-2cy) + rz*(-2cz)
    // Per distance: 1 FADD + 3 FFMA (fma pipe) + 2 FMNMX (alu pipe).
    // Cols consumed in chunks of CCH so peak register liveness fits without
    // ptxas demoting tile values back to shared in the inner loop.
#pragma unroll
    for (int jc = 0; jc < CT / CCH; jc++) {
        float cx[CCH], cy[CCH], cz[CCH], cn[CCH];
#pragma unroll
        for (int q = 0; q < CCH; q++) {
            const int c = tx * CT + jc * CCH + q;
            cx[q] = scx2[c]; cy[q] = scy2[c]; cz[q] = scz2[c]; cn[q] = scn[c];
        }
#pragma unroll
        for (int i = 0; i < RT; i++) {
#pragma unroll
            for (int q = 0; q < CCH; q++) {
                float d = rn[i] + cn[q];
                d = fmaf(rx[i], cx[q], d);
                d = fmaf(ry[i], cy[q], d);
                d = fmaf(rz[i], cz[q], d);
                rmin[i] = fminf(rmin[i], d);
                cmin[jc * CCH + q] = fminf(cmin[jc * CCH + q], d);
            }
        }
    }

    // Row mins across tx (16 lanes within the warp half), publish keys.
#pragma unroll
    for (int i = 0; i < RT; i++) {
        float v = rmin[i];
        v = fminf(v, __shfl_xor_sync(0xFFFFFFFFu, v, 1));
        v = fminf(v, __shfl_xor_sync(0xFFFFFFFFu, v, 2));
        v = fminf(v, __shfl_xor_sync(0xFFFFFFFFu, v, 4));
        v = fminf(v, __shfl_xor_sync(0xFFFFFFFFu, v, 8));
        rmin[i] = v;
    }
    if (tx == 0) {
#pragma unroll
        for (int i = 0; i < RT; i++)
            srowkey[ty * RT + i] = ~__float_as_uint(fmaxf(rmin[i], 0.0f));
    }

    // Col mins: fold the warp's two ty, then shared atomicMax across warps.
#pragma unroll
    for (int j = 0; j < CT; j++)
        cmin[j] = fminf(cmin[j], __shfl_xor_sync(0xFFFFFFFFu, cmin[j], 16));
    if ((t & 16) == 0) {
#pragma unroll
        for (int j = 0; j < CT; j++)
            atomicMax(&scolkey[tx * CT + j], ~__float_as_uint(fmaxf(cmin[j], 0.0f)));
    }
    __syncthreads();

    // Publish partial mins to global scratch (max on inverted bits == float min).
    if (t < TILE) {
        atomicMax(&g_key[b * NP + row0 + t], srowkey[t]);
    } else {
        const int u = t - TILE;
        atomicMax(&g_key[NB * NP + b * NP + col0 + u], scolkey[u]);
    }

    // ---- last-block fused reduction ----
    __threadfence();
    __syncthreads();
    if (t == 0) {
        unsigned ticket = atomicAdd(&g_count, 1u);
        is_last = (ticket == (unsigned)(NBLK - 1));
    }
    __syncthreads();
    if (!is_last) return;

    // All prior blocks' atomics are visible (fence + ticket). Sum and reset.
    float s = 0.0f;
    const uint4* pk = (const uint4*)g_key;
    uint4* pw = (uint4*)g_key;
    const uint4 zero4 = make_uint4(0u, 0u, 0u, 0u);
    for (int i = t; i < NMIN / 4; i += 256) {
        uint4 v = __ldcg(&pk[i]);
        s += __uint_as_float(~v.x) + __uint_as_float(~v.y)
           + __uint_as_float(~v.z) + __uint_as_float(~v.w);
        pw[i] = zero4;
    }
#pragma unroll
    for (int m = 16; m; m >>= 1)
        s += __shfl_xor_sync(0xFFFFFFFFu, s, m);
    if ((t & 31) == 0) red[t >> 5] = s;
    __syncthreads();
    if (t == 0) {
        float total = 0.0f;
#pragma unroll
        for (int w = 0; w < 8; w++) total += red[w];
        out[0] = total * (1.0f / (float)(NB * NP));
        g_count = 0u;   // reset for next graph replay
    }
}

extern "C" void kernel_launch(void* const* d_in, const int* in_sizes, int n_in,
                              void* d_out, int out_size) {
    (void)in_sizes; (void)n_in; (void)out_size;
    const float* coord = (const float*)d_in[0];  // [B, N, 3]
    const float* gt    = (const float*)d_in[1];  // [B, M, 3]
    dim3 grid(NP / TILE, NP / TILE, NB);         // (32, 32, 4) = 4096 blocks
    chamfer_fused_kernel<<<grid, 256>>>(coord, gt, (float*)d_out);
}

// round 14
// speedup vs baseline: 1.2685x; 1.2685x over previous
#include <cuda_runtime.h>

#define NB   4
#define NP   4096
#define TILE 128
#define RT   8
#define CT   8
#define CCH  4                                   // col chunk (register-liveness cap)
#define NMIN (2 * NB * NP)                       // 32768 mins: [gt | coord]

// Scratch, zero-initialized at module load. Keys are ~float_bits(d) so the
// atomicMax identity is 0 — no init kernel needed. The reduce kernel resets
// everything to 0 after reading, so every graph replay starts clean.
__device__ unsigned g_key[NMIN];

__global__ __launch_bounds__(256) void chamfer_tile_kernel(
    const float* __restrict__ coord, const float* __restrict__ gt)
{
    __shared__ float sgx[TILE], sgy[TILE], sgz[TILE], sgn[TILE];
    __shared__ float scx2[TILE], scy2[TILE], scz2[TILE], scn[TILE];
    __shared__ unsigned srowkey[TILE];
    __shared__ unsigned scolkey[TILE];

    const int b    = blockIdx.z;
    const int row0 = blockIdx.y * TILE;   // gt rows
    const int col0 = blockIdx.x * TILE;   // coord cols
    const int t    = threadIdx.x;

    // Stage tiles. Coord side pre-transformed: (-2x,-2y,-2z, |c|^2).
    if (t < TILE) {
        const float* p = gt + (size_t)(b * NP + row0 + t) * 3;
        const float x = p[0], y = p[1], z = p[2];
        sgx[t] = x; sgy[t] = y; sgz[t] = z;
        sgn[t] = fmaf(x, x, fmaf(y, y, z * z));
        scolkey[t] = 0u;
    } else {
        const int u = t - TILE;
        const float* p = coord + (size_t)(b * NP + col0 + u) * 3;
        const float x = p[0], y = p[1], z = p[2];
        scx2[u] = -2.0f * x; scy2[u] = -2.0f * y; scz2[u] = -2.0f * z;
        scn[u]  = fmaf(x, x, fmaf(y, y, z * z));
    }
    __syncthreads();

    const int ty = t >> 4;
    const int tx = t & 15;

    float rx[RT], ry[RT], rz[RT], rn[RT];
#pragma unroll
    for (int i = 0; i < RT; i++) {
        const int r = ty * RT + i;
        rx[i] = sgx[r]; ry[i] = sgy[r]; rz[i] = sgz[r]; rn[i] = sgn[r];
    }

    const float INF = __int_as_float(0x7F800000);
    float rmin[RT], cmin[CT];
#pragma unroll
    for (int i = 0; i < RT; i++) rmin[i] = INF;
#pragma unroll
    for (int j = 0; j < CT; j++) cmin[j] = INF;

    // d = (rn + cn) + rx*(-2cx) + ry*(-2cy) + rz*(-2cz)
    // Per distance: 1 FADD + 3 FFMA (fma pipe) + 2 FMNMX (alu pipe).
    // Cols consumed in chunks of CCH so peak register liveness stays well
    // under the default ceiling (no demotion to shared in the inner loop).
#pragma unroll
    for (int jc = 0; jc < CT / CCH; jc++) {
        float cx[CCH], cy[CCH], cz[CCH], cn[CCH];
#pragma unroll
        for (int q = 0; q < CCH; q++) {
            const int c = tx * CT + jc * CCH + q;
            cx[q] = scx2[c]; cy[q] = scy2[c]; cz[q] = scz2[c]; cn[q] = scn[c];
        }
#pragma unroll
        for (int i = 0; i < RT; i++) {
#pragma unroll
            for (int q = 0; q < CCH; q++) {
                float d = rn[i] + cn[q];
                d = fmaf(rx[i], cx[q], d);
                d = fmaf(ry[i], cy[q], d);
                d = fmaf(rz[i], cz[q], d);
                rmin[i] = fminf(rmin[i], d);
                cmin[jc * CCH + q] = fminf(cmin[jc * CCH + q], d);
            }
        }
    }

    // Row mins across tx (16 lanes within the warp half), publish keys.
#pragma unroll
    for (int i = 0; i < RT; i++) {
        float v = rmin[i];
        v = fminf(v, __shfl_xor_sync(0xFFFFFFFFu, v, 1));
        v = fminf(v, __shfl_xor_sync(0xFFFFFFFFu, v, 2));
        v = fminf(v, __shfl_xor_sync(0xFFFFFFFFu, v, 4));
        v = fminf(v, __shfl_xor_sync(0xFFFFFFFFu, v, 8));
        rmin[i] = v;
    }
    if (tx == 0) {
#pragma unroll
        for (int i = 0; i < RT; i++)
            srowkey[ty * RT + i] = ~__float_as_uint(fmaxf(rmin[i], 0.0f));
    }

    // Col mins: fold the warp's two ty, then shared atomicMax across warps.
#pragma unroll
    for (int j = 0; j < CT; j++)
        cmin[j] = fminf(cmin[j], __shfl_xor_sync(0xFFFFFFFFu, cmin[j], 16));
    if ((t & 16) == 0) {
#pragma unroll
        for (int j = 0; j < CT; j++)
            atomicMax(&scolkey[tx * CT + j], ~__float_as_uint(fmaxf(cmin[j], 0.0f)));
    }
    __syncthreads();

    // Publish partial mins (max on inverted bits == float min). No fence,
    // no fused tail — kernel boundary orders these before the reduce kernel.
    if (t < TILE) {
        atomicMax(&g_key[b * NP + row0 + t], srowkey[t]);
    } else {
        const int u = t - TILE;
        atomicMax(&g_key[NB * NP + b * NP + col0 + u], scolkey[u]);
    }
}

__global__ __launch_bounds__(1024) void reduce_kernel(float* __restrict__ out) {
    __shared__ float red[32];
    const int t = threadIdx.x;
    float s = 0.0f;
    const uint4* pk = (const uint4*)g_key;
    uint4* pw = (uint4*)g_key;
    const uint4 zero4 = make_uint4(0u, 0u, 0u, 0u);
#pragma unroll
    for (int it = 0; it < NMIN / 4 / 1024; it++) {
        const int i = it * 1024 + t;
        uint4 v = pk[i];
        s += __uint_as_float(~v.x) + __uint_as_float(~v.y)
           + __uint_as_float(~v.z) + __uint_as_float(~v.w);
        pw[i] = zero4;   // reset for next graph replay
    }
#pragma unroll
    for (int m = 16; m; m >>= 1)
        s += __shfl_xor_sync(0xFFFFFFFFu, s, m);
    if ((t & 31) == 0) red[t >> 5] = s;
    __syncthreads();
    if (t < 32) {
        float v = red[t];
#pragma unroll
        for (int m = 16; m; m >>= 1)
            v += __shfl_xor_sync(0xFFFFFFFFu, v, m);
        if (t == 0)
            // mean(match_coord) + mean(match_gt); B*M == B*N == 16384
            out[0] = v * (1.0f / (float)(NB * NP));
    }
}

extern "C" void kernel_launch(void* const* d_in, const int* in_sizes, int n_in,
                              void* d_out, int out_size) {
    (void)in_sizes; (void)n_in; (void)out_size;
    const float* coord = (const float*)d_in[0];  // [B, N, 3]
    const float* gt    = (const float*)d_in[1];  // [B, M, 3]
    dim3 grid(NP / TILE, NP / TILE, NB);         // (32, 32, 4) = 4096 blocks
    chamfer_tile_kernel<<<grid, 256>>>(coord, gt);
    reduce_kernel<<<1, 1024>>>((float*)d_out);
}

// round 16
// speedup vs baseline: 1.4205x; 1.1198x over previous
#include <cuda_runtime.h>

#define NB    4
#define NP    4096
#define TR    128                   // rows per block
#define CB    1024                  // cols per block
#define CTILE 128                   // cols per inner tile
#define NTC   (CB / CTILE)          // 8 inner tiles
#define RT    8                     // rows per thread
#define CT    8                     // cols per thread per tile
#define CCH   4                     // col chunk (register-liveness cap)
#define NMIN  (2 * NB * NP)         // 32768 mins: [gt rows | coord cols]

// Keys are ~float_bits(d): atomicMax identity is 0 == the zero-initialized
// state. The reduce kernel resets to 0 after reading (graph-replay clean).
__device__ unsigned g_key[NMIN];

__global__ __launch_bounds__(256) void chamfer_tile_kernel(
    const float* __restrict__ coord, const float* __restrict__ gt,
    float* __restrict__ out)
{
    __shared__ float sgx[TR], sgy[TR], sgz[TR], sgn[TR];
    __shared__ float scx2[CB], scy2[CB], scz2[CB], scn[CB];
    __shared__ unsigned srk[TR];

    const int b    = blockIdx.z;
    const int row0 = blockIdx.y * TR;   // gt rows
    const int col0 = blockIdx.x * CB;   // coord cols
    const int t    = threadIdx.x;

    if (b == 0 && blockIdx.x == 0 && blockIdx.y == 0 && t == 0)
        out[0] = 0.0f;                  // reduce kernel accumulates into this

    // ---- stage once: 128 gt rows + 1024 coord cols (pre-transformed) ----
    if (t < TR) {
        const float* p = gt + (size_t)(b * NP + row0 + t) * 3;
        const float x = p[0], y = p[1], z = p[2];
        sgx[t] = x; sgy[t] = y; sgz[t] = z;
        sgn[t] = fmaf(x, x, fmaf(y, y, z * z));
        srk[t] = 0u;
    }
    for (int c = t; c < CB; c += 256) {
        const float* p = coord + (size_t)(b * NP + col0 + c) * 3;
        const float x = p[0], y = p[1], z = p[2];
        scx2[c] = -2.0f * x; scy2[c] = -2.0f * y; scz2[c] = -2.0f * z;
        scn[c]  = fmaf(x, x, fmaf(y, y, z * z));
    }
    __syncthreads();

    // txr indexes rows (persistent mins, folded once at block end);
    // tyc indexes cols (folded per tile via shfl across txr lanes).
    const int tyc = t >> 4;             // 0..15
    const int txr = t & 15;             // 0..15 (lane bits 0-3)

    float rx[RT], ry[RT], rz[RT], rn[RT];
#pragma unroll
    for (int i = 0; i < RT; i++) {
        const int r = txr + 16 * i;     // strided: conflict-free LDS
        rx[i] = sgx[r]; ry[i] = sgy[r]; rz[i] = sgz[r]; rn[i] = sgn[r];
    }

    const float INF = __int_as_float(0x7F800000);
    float rmin[RT];
#pragma unroll
    for (int i = 0; i < RT; i++) rmin[i] = INF;

    // ---- 8 col tiles, no syncs: d = (rn+cn) -2(rx cx + ry cy + rz cz) ----
#pragma unroll
    for (int kt = 0; kt < NTC; kt++) {
        const int base = kt * CTILE;
        float cm[CT];
#pragma unroll
        for (int q = 0; q < CT; q++) cm[q] = INF;

#pragma unroll
        for (int q0 = 0; q0 < CT; q0 += CCH) {
            float cx[CCH], cy[CCH], cz[CCH], cn[CCH];
#pragma unroll
            for (int qq = 0; qq < CCH; qq++) {
                const int c = base + tyc + 16 * (q0 + qq);  // strided: no conflicts
                cx[qq] = scx2[c]; cy[qq] = scy2[c]; cz[qq] = scz2[c]; cn[qq] = scn[c];
            }
#pragma unroll
            for (int i = 0; i < RT; i++) {
#pragma unroll
                for (int qq = 0; qq < CCH; qq++) {
                    float d = rn[i] + cn[qq];
                    d = fmaf(rx[i], cx[qq], d);
                    d = fmaf(ry[i], cy[qq], d);
                    d = fmaf(rz[i], cz[qq], d);
                    rmin[i] = fminf(rmin[i], d);
                    cm[q0 + qq] = fminf(cm[q0 + qq], d);
                }
            }
        }

        // Fold col mins across txr (lane bits 0-3), publish one REDG per col.
#pragma unroll
        for (int q = 0; q < CT; q++) {
            float v = cm[q];
            v = fminf(v, __shfl_xor_sync(0xFFFFFFFFu, v, 1));
            v = fminf(v, __shfl_xor_sync(0xFFFFFFFFu, v, 2));
            v = fminf(v, __shfl_xor_sync(0xFFFFFFFFu, v, 4));
            v = fminf(v, __shfl_xor_sync(0xFFFFFFFFu, v, 8));
            cm[q] = v;
        }
        if (txr == 0) {
#pragma unroll
            for (int q = 0; q < CT; q++) {
                const int c = base + tyc + 16 * q;
                atomicMax(&g_key[NB * NP + b * NP + col0 + c],
                          ~__float_as_uint(fmaxf(cm[q], 0.0f)));
            }
        }
    }

    // ---- row mins: smem fold across tyc groups, publish once per row ----
#pragma unroll
    for (int i = 0; i < RT; i++)
        atomicMax(&srk[txr + 16 * i], ~__float_as_uint(fmaxf(rmin[i], 0.0f)));
    __syncthreads();
    if (t < TR)
        atomicMax(&g_key[b * NP + row0 + t], srk[t]);
}

__global__ __launch_bounds__(256) void reduce_kernel(float* __restrict__ out) {
    __shared__ float red[8];
    const int t   = threadIdx.x;
    const int idx = blockIdx.x * 256 + t;        // 32 blocks x 256 = 8192 uint4
    const uint4* pk = (const uint4*)g_key;
    uint4* pw = (uint4*)g_key;
    uint4 v = pk[idx];
    float s = __uint_as_float(~v.x) + __uint_as_float(~v.y)
            + __uint_as_float(~v.z) + __uint_as_float(~v.w);
    pw[idx] = make_uint4(0u, 0u, 0u, 0u);        // reset for next graph replay
#pragma unroll
    for (int m = 16; m; m >>= 1)
        s += __shfl_xor_sync(0xFFFFFFFFu, s, m);
    if ((t & 31) == 0) red[t >> 5] = s;
    __syncthreads();
    if (t == 0) {
        float tot = 0.0f;
#pragma unroll
        for (int w = 0; w < 8; w++) tot += red[w];
        // mean(match_coord) + mean(match_gt); B*M == B*N == 16384
        atomicAdd(out, tot * (1.0f / (float)(NB * NP)));
    }
}

extern "C" void kernel_launch(void* const* d_in, const int* in_sizes, int n_in,
                              void* d_out, int out_size) {
    (void)in_sizes; (void)n_in; (void)out_size;
    const float* coord = (const float*)d_in[0];  // [B, N, 3]
    const float* gt    = (const float*)d_in[1];  // [B, M, 3]
    dim3 grid(NP / CB, NP / TR, NB);             // (4, 32, 4) = 512 blocks
    chamfer_tile_kernel<<<grid, 256>>>(coord, gt, (float*)d_out);
    reduce_kernel<<<32, 256>>>((float*)d_out);
}